// round 7
// baseline (speedup 1.0000x reference)
#include <cuda_runtime.h>
#include <math.h>

#define BB 32
#define TT 512
#define HH 1024
#define LL 256
#define VV 13

// ---- scratch (static device globals: no allocation allowed) ----
__device__ float g_h0[BB * HH];                 // 128 KB
__device__ float g_hs[(size_t)BB * TT * HH];    // 64 MB, layout [b][t][h]
__device__ float g_part[512];                   // per-CTA loss partials
__device__ unsigned g_bar;                      // software grid barrier counter

typedef unsigned long long ull;
union F4U { float4 f; ull u[2]; };

__device__ __forceinline__ void ffma2(ull& d, ull a, ull b) {
    asm("fma.rn.f32x2 %0, %1, %2, %0;" : "+l"(d) : "l"(a), "l"(b));
}
__device__ __forceinline__ float pair_sum(ull v) {
    float x, y;
    asm("mov.b64 {%0, %1}, %2;" : "=f"(x), "=f"(y) : "l"(v));
    return x + y;
}
__device__ __forceinline__ void unpack2(float& x, float& y, ull v) {
    asm("mov.b64 {%0, %1}, %2;" : "=f"(x), "=f"(y) : "l"(v));
}
__device__ __forceinline__ unsigned ld_acq(const unsigned* p) {
    unsigned v;
    asm volatile("ld.acquire.gpu.global.u32 %0, [%1];" : "=r"(v) : "l"(p) : "memory");
    return v;
}
__device__ __forceinline__ void red_rel(unsigned* p, unsigned v) {
    asm volatile("red.release.gpu.global.add.u32 [%0], %1;" :: "l"(p), "r"(v) : "memory");
}

// SMEM layout for k_lstm (dynamic)
// A: W_hh slice, 512 kp * 256B = 131072
// B: 16 warps * (32 rows * 144B) = 73728  (reused for split-K partials P:
//    256 rows * 144B = 36864)
#define SM_A     0
#define SM_B     131072
#define SM_BUF1  4608          // 32 kp-rows * 144
#define SM_BIAS  (SM_B + 16 * SM_BUF1)   // 204800
#define SM_TOTAL (SM_BIAS + 128)         // 204928

__global__ void k_zero() {
    if (threadIdx.x == 0 && blockIdx.x == 0) g_bar = 0u;
}

// ------------------------------------------------------------------
// h0 = relu(latent @ Wz^T + bz)
// ------------------------------------------------------------------
__global__ void k_h0(const float* __restrict__ latent,
                     const float* __restrict__ Wz,
                     const float* __restrict__ bz) {
    __shared__ float lat[LL];
    int b = blockIdx.x;
    for (int k = threadIdx.x; k < LL; k += blockDim.x) lat[k] = latent[b * LL + k];
    __syncthreads();
    for (int j = threadIdx.x; j < HH; j += blockDim.x) {
        const float4* w = (const float4*)(Wz + (size_t)j * LL);
        float s = bz[j];
#pragma unroll 8
        for (int k4 = 0; k4 < LL / 4; ++k4) {
            float4 wv = w[k4];
            s += wv.x * lat[k4 * 4 + 0] + wv.y * lat[k4 * 4 + 1]
               + wv.z * lat[k4 * 4 + 2] + wv.w * lat[k4 * 4 + 3];
        }
        g_h0[b * HH + j] = fmaxf(s, 0.f);
    }
}

// ------------------------------------------------------------------
// Persistent LSTM recurrence. 128 CTAs (1/SM), 512 threads (16 warps).
// Warp w = (kw = w>>1 : K slice of 128, bh = w&1 : batch half of 16).
// Lane (lr = lane&7 unit, lb = lane>>3): acc tile = 4 gates x 4 batches
// (32 regs) -> no spills under the 128-reg cap (R6 tile spilled).
// A layout per kp (256B): [units x gates01 | units x gates23].
// B buffer rows interleaved (kp' = kp/2 + (kp&1)*16, pitch 144) so both
// staging STS.64 and compute LDS.128 are conflict-free and aligned.
// ------------------------------------------------------------------
__global__ void __launch_bounds__(512, 1) k_lstm(
    const float* __restrict__ W_hh,   // [4H, H]
    const float* __restrict__ W_ih,   // [4H, V]
    const float* __restrict__ b_ih,
    const float* __restrict__ b_hh,
    const int*   __restrict__ labels) // [B, T]
{
    extern __shared__ char sm[];
    float* cbias = (float*)(sm + SM_BIAS);

    const int tid  = threadIdx.x;
    const int w    = tid >> 5;
    const int lane = tid & 31;
    const int kw   = w >> 1;      // k-split 0..7 (128 k each)
    const int bh   = w & 1;       // batch half (16 batches)
    const int lr   = lane & 7;    // unit within CTA
    const int lb   = lane >> 3;   // batch quad within half (4 batches)
    const int u0   = blockIdx.x * 8;

    // ---- one-time: W_hh slice -> SMEM, gate-pair-split layout ----
    for (int i = tid; i < 32 * 512; i += 512) {
        int kp = i & 511, row = i >> 9;       // row = u*4+g
        int u = row >> 2, g = row & 3;
        char* dst = sm + kp * 256 + ((g >> 1) << 7) + u * 16 + ((g & 1) << 3);
        *(float2*)dst = *(const float2*)(W_hh + (size_t)(g * HH + u0 + u) * HH + 2 * kp);
    }
    if (tid < 32) {
        int u = tid >> 2, g = tid & 3;
        cbias[tid] = b_ih[g * HH + u0 + u] + b_hh[g * HH + u0 + u];
    }

    const int pu = tid & 7;       // pointwise: unit (tid < 256 only)
    const int pb = tid >> 3;      // pointwise: batch 0..31
    float c_loc = 0.f;
    char* buf = sm + SM_B + w * SM_BUF1;
    __syncthreads();

    for (int t = 0; t < TT; ++t) {
        if (t > 0) {
            if (tid == 0) {
                unsigned tgt = 128u * (unsigned)t;
                while (ld_acq(&g_bar) < tgt) {}
            }
            __syncthreads();   // also: P reads done before buf re-staging
        }

        // staging bases: lane covers 4 batch rows (one per quad j),
        // 8 lanes cover 128B contiguous per row -> fully coalesced.
        const float* base[4];
#pragma unroll
        for (int j = 0; j < 4; ++j) {
            int bg = bh * 16 + j * 4 + lb;
            base[j] = ((t == 0) ? (g_h0 + bg * HH)
                                : (g_hs + ((size_t)bg * TT + (t - 1)) * HH))
                      + kw * 128 + lr * 4;
        }

        ull acc[4][4];
#pragma unroll
        for (int g = 0; g < 4; ++g)
#pragma unroll
            for (int c = 0; c < 4; ++c) acc[g][c] = 0ull;

        float4 v[8];
        // prefetch sub-chunk 0 (k = kw*128 .. +64)
#pragma unroll
        for (int j = 0; j < 4; ++j) {
            v[j * 2 + 0] = *(const float4*)(base[j]);
            v[j * 2 + 1] = *(const float4*)(base[j] + 32);
        }

#pragma unroll
        for (int sc = 0; sc < 2; ++sc) {
            // store staged 64 k: kp = c*16 + 2*lr (+1), row = kp/2 + (kp&1)*16
#pragma unroll
            for (int j = 0; j < 4; ++j) {
#pragma unroll
                for (int c = 0; c < 2; ++c) {
                    float4 q = v[j * 2 + c];
                    int bl = j * 4 + lb;                   // batch 0..15 in half
                    int r0 = c * 8 + lr;                   // even-kp row
                    *(float2*)(buf + r0 * 144 + bl * 8)        = make_float2(q.x, q.y);
                    *(float2*)(buf + (r0 + 16) * 144 + bl * 8) = make_float2(q.z, q.w);
                }
            }
            __syncwarp();
            if (sc == 0) {   // prefetch sub-chunk 1 while computing 0
#pragma unroll
                for (int j = 0; j < 4; ++j) {
                    v[j * 2 + 0] = *(const float4*)(base[j] + 64);
                    v[j * 2 + 1] = *(const float4*)(base[j] + 96);
                }
            }
            const char* Ab = sm + (size_t)(kw * 64 + sc * 32) * 256;
#pragma unroll
            for (int kp = 0; kp < 32; ++kp) {
                F4U qa0, qa1;
                qa0.f = *(const float4*)(Ab + kp * 256 + lr * 16);        // gates 0,1
                qa1.f = *(const float4*)(Ab + kp * 256 + 128 + lr * 16);  // gates 2,3
                const int brow = (kp >> 1) + ((kp & 1) << 4);
                const char* bp = buf + brow * 144 + lb * 32;
                F4U q0, q1;
                q0.f = *(const float4*)(bp);
                q1.f = *(const float4*)(bp + 16);
                ull a0 = qa0.u[0], a1 = qa0.u[1], a2 = qa1.u[0], a3 = qa1.u[1];
                ull b0 = q0.u[0], b1 = q0.u[1], b2 = q1.u[0], b3 = q1.u[1];
                ffma2(acc[0][0], a0, b0); ffma2(acc[0][1], a0, b1);
                ffma2(acc[0][2], a0, b2); ffma2(acc[0][3], a0, b3);
                ffma2(acc[1][0], a1, b0); ffma2(acc[1][1], a1, b1);
                ffma2(acc[1][2], a1, b2); ffma2(acc[1][3], a1, b3);
                ffma2(acc[2][0], a2, b0); ffma2(acc[2][1], a2, b1);
                ffma2(acc[2][2], a2, b2); ffma2(acc[2][3], a2, b3);
                ffma2(acc[3][0], a3, b0); ffma2(acc[3][1], a3, b1);
                ffma2(acc[3][2], a3, b2); ffma2(acc[3][3], a3, b3);
            }
            __syncwarp();
        }

        // ---- split-K partials (8-way): P row = kw*32 + bg, pitch 144 ----
        __syncthreads();   // all warps done reading their buffers
        char* P = sm + SM_B;
#pragma unroll
        for (int c = 0; c < 4; ++c) {
            int bg = bh * 16 + lb * 4 + c;
            float4 g4 = make_float4(pair_sum(acc[0][c]), pair_sum(acc[1][c]),
                                    pair_sum(acc[2][c]), pair_sum(acc[3][c]));
            *(float4*)(P + (kw * 32 + bg) * 144 + lr * 16) = g4;
        }
        __syncthreads();

        // ---- reduce over 8 k-splits + pointwise cell (i,f,g,o) ----
        if (tid < 256) {
            float4 s = make_float4(0.f, 0.f, 0.f, 0.f);
#pragma unroll
            for (int k8 = 0; k8 < 8; ++k8) {
                float4 pv = *(const float4*)(P + (k8 * 32 + pb) * 144 + pu * 16);
                s.x += pv.x; s.y += pv.y; s.z += pv.z; s.w += pv.w;
            }
            float gi = s.x + cbias[pu * 4 + 0];
            float gf = s.y + cbias[pu * 4 + 1];
            float gg = s.z + cbias[pu * 4 + 2];
            float go = s.w + cbias[pu * 4 + 3];
            if (t > 0) {   // one-hot input = column gather of W_ih
                int lbl = labels[pb * TT + t - 1];
                int ub  = u0 + pu;
                gi += W_ih[(size_t)(0 * HH + ub) * VV + lbl];
                gf += W_ih[(size_t)(1 * HH + ub) * VV + lbl];
                gg += W_ih[(size_t)(2 * HH + ub) * VV + lbl];
                go += W_ih[(size_t)(3 * HH + ub) * VV + lbl];
            }
            float is = 1.f / (1.f + expf(-gi));
            float fs = 1.f / (1.f + expf(-gf));
            float gt = tanhf(gg);
            float os = 1.f / (1.f + expf(-go));
            c_loc = fs * c_loc + is * gt;
            g_hs[((size_t)pb * TT + t) * HH + u0 + pu] = os * tanhf(c_loc);
        }
        __syncthreads();   // h writes + P reads done before release
        if (tid == 0) red_rel(&g_bar, 1u);
    }
}

// ------------------------------------------------------------------
// Output head (known-good from R6): 256 threads, 64 rows/CTA, f32x2.
// ------------------------------------------------------------------
#define OKC 32
#define FP2 33   // Fs2 pitch in float2
#define WT 68
#define ASP 66
#define WOP 66

__global__ void __launch_bounds__(256) k_out(
    const float* __restrict__ latent,
    const int*   __restrict__ labels,
    const int*   __restrict__ lengths,
    const float* __restrict__ Wnl,   // [H, H+L]
    const float* __restrict__ bnl,
    const float* __restrict__ Wout,  // [V, H]
    const float* __restrict__ bout)
{
    __shared__ char FsA[64 * FP2 * 8];   // Fs2 during GEMM, aS in epilogue
    __shared__ float Wst[OKC * WT];
    __shared__ float Wos[VV * WOP];
    __shared__ float Ls[64 * 16];
    __shared__ float lat_s[LL];
    __shared__ float red2[2];

    float2* Fs2 = (float2*)FsA;
    float*  aS  = (float*)FsA;

    const int tid = threadIdx.x;
    const int r0 = blockIdx.x * 64;
    const int b = r0 / TT;
    const int txj = tid & 15;
    const int tyr = tid >> 4;

    for (int idx = tid; idx < 64 * 16; idx += 256) Ls[idx] = 0.f;
    for (int k = tid; k < LL; k += 256) lat_s[k] = latent[b * LL + k];

    for (int jc = 0; jc < HH; jc += 64) {
        ull accp[4][2] = {};
        for (int kc = 0; kc < HH + LL; kc += OKC) {
            __syncthreads();
#pragma unroll
            for (int q = 0; q < 8; ++q) {
                int i = q * 256 + tid;
                int k = i & 31;
                int row = i >> 5;
                int kk = kc + k;
                float v = (kk < HH) ? g_hs[(size_t)(r0 + row) * HH + kk]
                                    : lat_s[kk - HH];
                Fs2[row * FP2 + k] = make_float2(v, v);
            }
#pragma unroll
            for (int q = 0; q < 2; ++q) {
                int i = q * 256 + tid;
                int jl = i >> 3;
                int kq = (i & 7) << 2;
                float4 v = *(const float4*)(Wnl + (size_t)(jc + jl) * (HH + LL) + kc + kq);
                Wst[(kq + 0) * WT + jl] = v.x;
                Wst[(kq + 1) * WT + jl] = v.y;
                Wst[(kq + 2) * WT + jl] = v.z;
                Wst[(kq + 3) * WT + jl] = v.w;
            }
            __syncthreads();
#pragma unroll 4
            for (int k = 0; k < OKC; ++k) {
                F4U qw;
                qw.f = *(const float4*)(Wst + k * WT + (txj << 2));
                ull b0 = qw.u[0], b1 = qw.u[1];
#pragma unroll
                for (int r = 0; r < 4; ++r) {
                    ull fd = *(const ull*)(Fs2 + (tyr * 4 + r) * FP2 + k);
                    ffma2(accp[r][0], fd, b0);
                    ffma2(accp[r][1], fd, b1);
                }
            }
        }
        __syncthreads();
#pragma unroll
        for (int r = 0; r < 4; ++r) {
            float a0, a1, a2, a3;
            unpack2(a0, a1, accp[r][0]);
            unpack2(a2, a3, accp[r][1]);
            int j = txj << 2;
            int row = tyr * 4 + r;
            aS[row * ASP + j + 0] = fmaxf(a0 + bnl[jc + j + 0], 0.f);
            aS[row * ASP + j + 1] = fmaxf(a1 + bnl[jc + j + 1], 0.f);
            aS[row * ASP + j + 2] = fmaxf(a2 + bnl[jc + j + 2], 0.f);
            aS[row * ASP + j + 3] = fmaxf(a3 + bnl[jc + j + 3], 0.f);
        }
        for (int idx = tid; idx < VV * 64; idx += 256) {
            int v = idx >> 6, jl = idx & 63;
            Wos[v * WOP + jl] = Wout[(size_t)v * HH + jc + jl];
        }
        __syncthreads();
        for (int idx = tid; idx < 64 * VV; idx += 256) {
            int row = idx / VV, v = idx - row * VV;
            float s = 0.f;
#pragma unroll 8
            for (int jl = 0; jl < 64; ++jl)
                s += aS[row * ASP + jl] * Wos[v * WOP + jl];
            Ls[row * 16 + v] += s;
        }
        __syncthreads();
    }

    float val = 0.f;
    if (tid < 64) {
        int row = tid;
        int t = (r0 + row) % TT;
        float m = -1e30f;
#pragma unroll
        for (int v = 0; v < VV; ++v) m = fmaxf(m, Ls[row * 16 + v] + bout[v]);
        float s = 0.f;
#pragma unroll
        for (int v = 0; v < VV; ++v) s += expf(Ls[row * 16 + v] + bout[v] - m);
        float lse = m + logf(s);
        int lbl = labels[b * TT + t];
        float nll = lse - (Ls[row * 16 + lbl] + bout[lbl]);
        if (t < lengths[b]) val = nll;
#pragma unroll
        for (int o = 16; o > 0; o >>= 1) val += __shfl_down_sync(0xffffffffu, val, o);
        if ((tid & 31) == 0) red2[tid >> 5] = val;
    }
    __syncthreads();
    if (tid == 0) g_part[blockIdx.x] = red2[0] + red2[1];
}

// ------------------------------------------------------------------
__global__ void k_final(float* __restrict__ out, int out_size) {
    int b = threadIdx.x;   // 0..31
    float s = 0.f;
#pragma unroll
    for (int i = 0; i < 8; ++i) s += g_part[b * 8 + i];
    if (1 + b < out_size) out[1 + b] = s;
    float tot = s;
#pragma unroll
    for (int o = 16; o > 0; o >>= 1) tot += __shfl_down_sync(0xffffffffu, tot, o);
    if (b == 0) out[0] = tot;
}

// ------------------------------------------------------------------
extern "C" void kernel_launch(void* const* d_in, const int* in_sizes, int n_in,
                              void* d_out, int out_size) {
    const float* latent  = (const float*)d_in[1];
    const int*   labels  = (const int*)d_in[2];
    const int*   lengths = (const int*)d_in[3];
    const float* W_ih    = (const float*)d_in[4];
    const float* W_hh    = (const float*)d_in[5];
    const float* b_ih    = (const float*)d_in[6];
    const float* b_hh    = (const float*)d_in[7];
    const float* Wz      = (const float*)d_in[8];
    const float* bz      = (const float*)d_in[9];
    const float* Wnl     = (const float*)d_in[10];
    const float* bnl     = (const float*)d_in[11];
    const float* Wout    = (const float*)d_in[12];
    const float* bout    = (const float*)d_in[13];
    float* out = (float*)d_out;

    cudaFuncSetAttribute(k_lstm, cudaFuncAttributeMaxDynamicSharedMemorySize, SM_TOTAL);

    k_zero<<<1, 32>>>();
    k_h0<<<BB, 256>>>(latent, Wz, bz);
    k_lstm<<<128, 512, SM_TOTAL>>>(W_hh, W_ih, b_ih, b_hh, labels);
    k_out<<<(BB * TT) / 64, 256>>>(latent, labels, lengths, Wnl, bnl, Wout, bout);
    k_final<<<1, 32>>>(out, out_size);
}

// round 11
// speedup vs baseline: 1.8228x; 1.8228x over previous
#include <cuda_runtime.h>
#include <cuda_bf16.h>
#include <math.h>

#define BB 32
#define TT 512
#define HH 1024
#define LL 256
#define VV 13

// ---- scratch (static device globals: no allocation allowed) ----
__device__ float g_hs[(size_t)BB * TT * HH];            // 64 MB [b][t][h]
__device__ float g_part[512];                           // per-CTA loss partials
__device__ unsigned g_bar;                              // grid barrier counter
__device__ __align__(16) __nv_bfloat16 g_hb[2][BB * HH]; // h bf16 images [buf][b][k]
__device__ float g_wih_t[VV * 4 * HH];                  // W_ih transposed [v][4H]

typedef unsigned long long ull;

__device__ __forceinline__ unsigned ld_acq(const unsigned* p) {
    unsigned v;
    asm volatile("ld.acquire.gpu.global.u32 %0, [%1];" : "=r"(v) : "l"(p) : "memory");
    return v;
}
__device__ __forceinline__ void red_rel(unsigned* p, unsigned v) {
    asm volatile("red.release.gpu.global.add.u32 [%0], %1;" :: "l"(p), "r"(v) : "memory");
}
__device__ __forceinline__ unsigned pack_bf2(float lo, float hi) {
    __nv_bfloat162 v = __floats2bfloat162_rn(lo, hi);
    return *(unsigned*)&v;
}
// HMMA m16n8k16 bf16, fp32 accumulate (baseline PTX, works on compute_103)
__device__ __forceinline__ void mma16816(float* c, const unsigned* a, const unsigned* b) {
    asm volatile(
        "mma.sync.aligned.m16n8k16.row.col.f32.bf16.bf16.f32 "
        "{%0,%1,%2,%3}, {%4,%5,%6,%7}, {%8,%9}, {%0,%1,%2,%3};\n"
        : "+f"(c[0]), "+f"(c[1]), "+f"(c[2]), "+f"(c[3])
        : "r"(a[0]), "r"(a[1]), "r"(a[2]), "r"(a[3]), "r"(b[0]), "r"(b[1]));
}

// SMEM for k_lstm_mma (dynamic):
// B buffers: 8 warps x (32 n-rows x 272B) = 69632 ; P overlays it after MMA
// (P = 64 rows x 132 floats = 33792B). cbias after.
#define BUF_W  8704
#define SM_CB  69632
#define SM_SZ  70144

__global__ void k_zero() {
    if (threadIdx.x == 0 && blockIdx.x == 0) g_bar = 0u;
}

// transpose W_ih to [v][4H] for coalesced label gathers
__global__ void k_prep2(const float* __restrict__ W_ih) {
    int idx = blockIdx.x * 256 + threadIdx.x;
    if (idx < VV * 4 * HH) {
        int v = idx >> 12, row = idx & 4095;
        g_wih_t[v * 4096 + row] = W_ih[(size_t)row * VV + v];
    }
}

// ------------------------------------------------------------------
// h0 = relu(latent @ Wz^T + bz) -> bf16 image buf 0 ([b][k])
// ------------------------------------------------------------------
__global__ void k_h0(const float* __restrict__ latent,
                     const float* __restrict__ Wz,
                     const float* __restrict__ bz) {
    __shared__ float lat[LL];
    int b = blockIdx.x;
    for (int k = threadIdx.x; k < LL; k += blockDim.x) lat[k] = latent[b * LL + k];
    __syncthreads();
    for (int j = threadIdx.x; j < HH; j += blockDim.x) {
        const float4* w = (const float4*)(Wz + (size_t)j * LL);
        float s = bz[j];
#pragma unroll 8
        for (int k4 = 0; k4 < LL / 4; ++k4) {
            float4 wv = w[k4];
            s += wv.x * lat[k4 * 4 + 0] + wv.y * lat[k4 * 4 + 1]
               + wv.z * lat[k4 * 4 + 2] + wv.w * lat[k4 * 4 + 3];
        }
        float h = fmaxf(s, 0.f);
        g_hb[0][b * HH + j] = __float2bfloat16(h);
    }
}

// ------------------------------------------------------------------
// Persistent HMMA LSTM. 128 CTAs (1/SM), 256 threads (8 warps).
// CTA m owns units [8m, 8m+8): M=32 gate rows (r = g*8+u).
// Warp w: K slice [128w, 128w+128). A fragments (bf16) in REGISTERS
// for the whole kernel (64 regs). Per step: stage h slice (8KB/warp),
// 64 HMMA + 64 LDS.32 per warp, split-K reduce via SMEM, pointwise.
// ------------------------------------------------------------------
__global__ void __launch_bounds__(256, 1) k_lstm_mma(
    const float* __restrict__ W_hh,   // [4H, H]
    const float* __restrict__ b_ih,
    const float* __restrict__ b_hh,
    const int*   __restrict__ labels) // [B, T]
{
    extern __shared__ char sm[];
    float* cbias = (float*)(sm + SM_CB);

    const int tid = threadIdx.x;
    const int w   = tid >> 5;
    const int l   = tid & 31;
    const int qr  = l >> 2;     // fragment row group 0..7
    const int qc  = l & 3;      // fragment k quad 0..3
    const int m   = blockIdx.x;
    const int k0  = w * 128;

    if (tid < 32) {   // cbias[u*4+g]
        int u = tid >> 2, g = tid & 3;
        cbias[tid] = b_ih[g * HH + m * 8 + u] + b_hh[g * HH + m * 8 + u];
    }

    // ---- one-time: A fragments (W_hh bf16) into registers ----
    // row r = g*8+u ; Mtile mt: rows mt*16..+16 (gates 2mt, 2mt+1)
    unsigned af[2][8][4];
#pragma unroll
    for (int mt = 0; mt < 2; ++mt) {
        const float* wlo = W_hh + (size_t)((mt * 2 + 0) * HH + m * 8 + qr) * HH;
        const float* whi = W_hh + (size_t)((mt * 2 + 1) * HH + m * 8 + qr) * HH;
#pragma unroll
        for (int ks = 0; ks < 8; ++ks) {
            int k = k0 + ks * 16 + qc * 2;
            af[mt][ks][0] = pack_bf2(wlo[k],     wlo[k + 1]);
            af[mt][ks][1] = pack_bf2(whi[k],     whi[k + 1]);
            af[mt][ks][2] = pack_bf2(wlo[k + 8], wlo[k + 9]);
            af[mt][ks][3] = pack_bf2(whi[k + 8], whi[k + 9]);
        }
    }

    const int pu = tid & 7;       // pointwise: unit
    const int pb = tid >> 3;      // pointwise: batch 0..31
    float c_loc = 0.f;
    char* bufw = sm + w * BUF_W;
    __syncthreads();

    for (int t = 0; t < TT; ++t) {
        if (t > 0) {
            if (tid == 0) {
                unsigned tgt = 128u * (unsigned)t;
                while (ld_acq(&g_bar) < tgt) {}
            }
            __syncthreads();   // also: P reads done before buf re-staging
        }

        // ---- stage B slice: all 32 batches, k in [k0, k0+128), bf16 ----
        {
            const char* src = (const char*)g_hb[t & 1] + k0 * 2;
            int nn = l >> 4, c = l & 15;   // 16 lanes cover 256B of one row
#pragma unroll
            for (int p = 0; p < 16; ++p) {
                int n = p * 2 + nn;
                *(float4*)(bufw + n * 272 + c * 16) =
                    *(const float4*)(src + (size_t)n * (HH * 2) + c * 16);
            }
        }
        __syncthreads();

        // ---- MMA: 8 ksteps x (2 mt x 4 nt) ----
        float acc[2][4][4] = {};
#pragma unroll
        for (int ks = 0; ks < 8; ++ks) {
            unsigned bf[4][2];
#pragma unroll
            for (int nt = 0; nt < 4; ++nt) {
                const char* bp = bufw + (nt * 8 + qr) * 272 + (ks * 16 + qc * 2) * 2;
                bf[nt][0] = *(const unsigned*)bp;          // k, k+1
                bf[nt][1] = *(const unsigned*)(bp + 16);   // k+8, k+9
            }
#pragma unroll
            for (int mt = 0; mt < 2; ++mt)
#pragma unroll
                for (int nt = 0; nt < 4; ++nt)
                    mma16816(acc[mt][nt], af[mt][ks], bf[nt]);
        }
        __syncthreads();   // all warps done reading B before P overlay

        // ---- split-K partials: P[(w*8+u)*132 + n*4 + g] ----
        float* P = (float*)sm;
#pragma unroll
        for (int mt = 0; mt < 2; ++mt) {
            float* base = P + (w * 8 + qr) * 132;   // u = qr
            int g_lo = mt * 2, g_hi = mt * 2 + 1;
#pragma unroll
            for (int nt = 0; nt < 4; ++nt) {
                int n0 = nt * 8 + qc * 2;
                base[(n0    ) * 4 + g_lo] = acc[mt][nt][0];
                base[(n0 + 1) * 4 + g_lo] = acc[mt][nt][1];
                base[(n0    ) * 4 + g_hi] = acc[mt][nt][2];
                base[(n0 + 1) * 4 + g_hi] = acc[mt][nt][3];
            }
        }
        __syncthreads();

        // ---- reduce 8 warps + pointwise cell (i,f,g,o) ----
        {
            float4 s = make_float4(0.f, 0.f, 0.f, 0.f);
#pragma unroll
            for (int ww = 0; ww < 8; ++ww) {
                float4 v = *(const float4*)(P + (ww * 8 + pu) * 132 + pb * 4);
                s.x += v.x; s.y += v.y; s.z += v.z; s.w += v.w;
            }
            float gi = s.x + cbias[pu * 4 + 0];
            float gf = s.y + cbias[pu * 4 + 1];
            float gg = s.z + cbias[pu * 4 + 2];
            float go = s.w + cbias[pu * 4 + 3];
            const int ug = m * 8 + pu;
            if (t > 0) {   // one-hot input = row gather of W_ih^T
                int lbl = labels[pb * TT + t - 1];
                const float* wr = g_wih_t + (size_t)lbl * 4096;
                gi += wr[0 * HH + ug];
                gf += wr[1 * HH + ug];
                gg += wr[2 * HH + ug];
                go += wr[3 * HH + ug];
            }
            float is = 1.f / (1.f + expf(-gi));
            float fs = 1.f / (1.f + expf(-gf));
            float gt = tanhf(gg);
            float os = 1.f / (1.f + expf(-go));
            c_loc = fs * c_loc + is * gt;
            float h = os * tanhf(c_loc);
            g_hs[((size_t)pb * TT + t) * HH + ug] = h;
            g_hb[(t + 1) & 1][pb * HH + ug] = __float2bfloat16(h);
        }
        __syncthreads();   // h writes + P reads done before release
        if (tid == 0) red_rel(&g_bar, 1u);
    }
}

// ------------------------------------------------------------------
// Output head (known-good R6): 256 threads, 64 rows/CTA, f32x2.
// ------------------------------------------------------------------
union F4U { float4 f; ull u[2]; };
__device__ __forceinline__ void ffma2(ull& d, ull a, ull b) {
    asm("fma.rn.f32x2 %0, %1, %2, %0;" : "+l"(d) : "l"(a), "l"(b));
}
__device__ __forceinline__ void unpack2(float& x, float& y, ull v) {
    asm("mov.b64 {%0, %1}, %2;" : "=f"(x), "=f"(y) : "l"(v));
}

#define OKC 32
#define FP2 33
#define WT 68
#define ASP 66
#define WOP 66

__global__ void __launch_bounds__(256) k_out(
    const float* __restrict__ latent,
    const int*   __restrict__ labels,
    const int*   __restrict__ lengths,
    const float* __restrict__ Wnl,
    const float* __restrict__ bnl,
    const float* __restrict__ Wout,
    const float* __restrict__ bout)
{
    __shared__ char FsA[64 * FP2 * 8];
    __shared__ float Wst[OKC * WT];
    __shared__ float Wos[VV * WOP];
    __shared__ float Ls[64 * 16];
    __shared__ float lat_s[LL];
    __shared__ float red2[2];

    float2* Fs2 = (float2*)FsA;
    float*  aS  = (float*)FsA;

    const int tid = threadIdx.x;
    const int r0 = blockIdx.x * 64;
    const int b = r0 / TT;
    const int txj = tid & 15;
    const int tyr = tid >> 4;

    for (int idx = tid; idx < 64 * 16; idx += 256) Ls[idx] = 0.f;
    for (int k = tid; k < LL; k += 256) lat_s[k] = latent[b * LL + k];

    for (int jc = 0; jc < HH; jc += 64) {
        ull accp[4][2] = {};
        for (int kc = 0; kc < HH + LL; kc += OKC) {
            __syncthreads();
#pragma unroll
            for (int q = 0; q < 8; ++q) {
                int i = q * 256 + tid;
                int k = i & 31;
                int row = i >> 5;
                int kk = kc + k;
                float v = (kk < HH) ? g_hs[(size_t)(r0 + row) * HH + kk]
                                    : lat_s[kk - HH];
                Fs2[row * FP2 + k] = make_float2(v, v);
            }
#pragma unroll
            for (int q = 0; q < 2; ++q) {
                int i = q * 256 + tid;
                int jl = i >> 3;
                int kq = (i & 7) << 2;
                float4 v = *(const float4*)(Wnl + (size_t)(jc + jl) * (HH + LL) + kc + kq);
                Wst[(kq + 0) * WT + jl] = v.x;
                Wst[(kq + 1) * WT + jl] = v.y;
                Wst[(kq + 2) * WT + jl] = v.z;
                Wst[(kq + 3) * WT + jl] = v.w;
            }
            __syncthreads();
#pragma unroll 4
            for (int k = 0; k < OKC; ++k) {
                F4U qw;
                qw.f = *(const float4*)(Wst + k * WT + (txj << 2));
                ull b0 = qw.u[0], b1 = qw.u[1];
#pragma unroll
                for (int r = 0; r < 4; ++r) {
                    ull fd = *(const ull*)(Fs2 + (tyr * 4 + r) * FP2 + k);
                    ffma2(accp[r][0], fd, b0);
                    ffma2(accp[r][1], fd, b1);
                }
            }
        }
        __syncthreads();
#pragma unroll
        for (int r = 0; r < 4; ++r) {
            float a0, a1, a2, a3;
            unpack2(a0, a1, accp[r][0]);
            unpack2(a2, a3, accp[r][1]);
            int j = txj << 2;
            int row = tyr * 4 + r;
            aS[row * ASP + j + 0] = fmaxf(a0 + bnl[jc + j + 0], 0.f);
            aS[row * ASP + j + 1] = fmaxf(a1 + bnl[jc + j + 1], 0.f);
            aS[row * ASP + j + 2] = fmaxf(a2 + bnl[jc + j + 2], 0.f);
            aS[row * ASP + j + 3] = fmaxf(a3 + bnl[jc + j + 3], 0.f);
        }
        for (int idx = tid; idx < VV * 64; idx += 256) {
            int v = idx >> 6, jl = idx & 63;
            Wos[v * WOP + jl] = Wout[(size_t)v * HH + jc + jl];
        }
        __syncthreads();
        for (int idx = tid; idx < 64 * VV; idx += 256) {
            int row = idx / VV, v = idx - row * VV;
            float s = 0.f;
#pragma unroll 8
            for (int jl = 0; jl < 64; ++jl)
                s += aS[row * ASP + jl] * Wos[v * WOP + jl];
            Ls[row * 16 + v] += s;
        }
        __syncthreads();
    }

    float val = 0.f;
    if (tid < 64) {
        int row = tid;
        int t = (r0 + row) % TT;
        float mx = -1e30f;
#pragma unroll
        for (int v = 0; v < VV; ++v) mx = fmaxf(mx, Ls[row * 16 + v] + bout[v]);
        float s = 0.f;
#pragma unroll
        for (int v = 0; v < VV; ++v) s += expf(Ls[row * 16 + v] + bout[v] - mx);
        float lse = mx + logf(s);
        int lbl = labels[b * TT + t];
        float nll = lse - (Ls[row * 16 + lbl] + bout[lbl]);
        if (t < lengths[b]) val = nll;
#pragma unroll
        for (int o = 16; o > 0; o >>= 1) val += __shfl_down_sync(0xffffffffu, val, o);
        if ((tid & 31) == 0) red2[tid >> 5] = val;
    }
    __syncthreads();
    if (tid == 0) g_part[blockIdx.x] = red2[0] + red2[1];
}

// ------------------------------------------------------------------
__global__ void k_final(float* __restrict__ out, int out_size) {
    int b = threadIdx.x;   // 0..31
    float s = 0.f;
#pragma unroll
    for (int i = 0; i < 8; ++i) s += g_part[b * 8 + i];
    if (1 + b < out_size) out[1 + b] = s;
    float tot = s;
#pragma unroll
    for (int o = 16; o > 0; o >>= 1) tot += __shfl_down_sync(0xffffffffu, tot, o);
    if (b == 0) out[0] = tot;
}

// ------------------------------------------------------------------
extern "C" void kernel_launch(void* const* d_in, const int* in_sizes, int n_in,
                              void* d_out, int out_size) {
    const float* latent  = (const float*)d_in[1];
    const int*   labels  = (const int*)d_in[2];
    const int*   lengths = (const int*)d_in[3];
    const float* W_ih    = (const float*)d_in[4];
    const float* W_hh    = (const float*)d_in[5];
    const float* b_ih    = (const float*)d_in[6];
    const float* b_hh    = (const float*)d_in[7];
    const float* Wz      = (const float*)d_in[8];
    const float* bz      = (const float*)d_in[9];
    const float* Wnl     = (const float*)d_in[10];
    const float* bnl     = (const float*)d_in[11];
    const float* Wout    = (const float*)d_in[12];
    const float* bout    = (const float*)d_in[13];
    float* out = (float*)d_out;

    cudaFuncSetAttribute(k_lstm_mma, cudaFuncAttributeMaxDynamicSharedMemorySize, SM_SZ);

    k_zero<<<1, 32>>>();
    k_prep2<<<(VV * 4 * HH + 255) / 256, 256>>>(W_ih);
    k_h0<<<BB, 256>>>(latent, Wz, bz);
    k_lstm_mma<<<128, 256, SM_SZ>>>(W_hh, b_ih, b_hh, labels);
    k_out<<<(BB * TT) / 64, 256>>>(latent, labels, lengths, Wnl, bnl, Wout, bout);
    k_final<<<1, 32>>>(out, out_size);
}

// round 12
// speedup vs baseline: 3.7177x; 2.0395x over previous
#include <cuda_runtime.h>
#include <cuda_bf16.h>
#include <math.h>

#define BB 32
#define TT 512
#define HH 1024
#define LL 256
#define VV 13

// ---- scratch (static device globals: no allocation allowed) ----
__device__ __align__(16) __nv_bfloat16 g_hsb[(size_t)BB * TT * HH]; // 32MB [b][t][h]
__device__ __align__(16) __nv_bfloat16 g_h0b[BB * HH];              // h0 bf16 [b][h]
__device__ __align__(16) __nv_bfloat16 g_wnlb[HH * (HH + LL)];      // Wnl bf16 [j][k]
__device__ __align__(16) __nv_bfloat16 g_latb[BB * LL];             // latent bf16
__device__ float g_wih_t[VV * 4 * HH];                              // W_ih^T [v][4H]
__device__ float g_part[512];
__device__ unsigned g_bar;

typedef unsigned long long ull;

__device__ __forceinline__ unsigned ld_acq(const unsigned* p) {
    unsigned v;
    asm volatile("ld.acquire.gpu.global.u32 %0, [%1];" : "=r"(v) : "l"(p) : "memory");
    return v;
}
__device__ __forceinline__ void red_rel(unsigned* p, unsigned v) {
    asm volatile("red.release.gpu.global.add.u32 [%0], %1;" :: "l"(p), "r"(v) : "memory");
}
__device__ __forceinline__ unsigned pack_bf2(float lo, float hi) {
    __nv_bfloat162 v = __floats2bfloat162_rn(lo, hi);
    return *(unsigned*)&v;
}
__device__ __forceinline__ unsigned smem_u32(const void* p) {
    unsigned a;
    asm("{ .reg .u64 t; cvta.to.shared.u64 t, %1; cvt.u32.u64 %0, t; }" : "=r"(a) : "l"(p));
    return a;
}
// HMMA m16n8k16 bf16 fp32-acc (baseline PTX; fragment layout validated R11)
__device__ __forceinline__ void mma16816(float* c, const unsigned* a, const unsigned* b) {
    asm volatile(
        "mma.sync.aligned.m16n8k16.row.col.f32.bf16.bf16.f32 "
        "{%0,%1,%2,%3}, {%4,%5,%6,%7}, {%8,%9}, {%0,%1,%2,%3};\n"
        : "+f"(c[0]), "+f"(c[1]), "+f"(c[2]), "+f"(c[3])
        : "r"(a[0]), "r"(a[1]), "r"(a[2]), "r"(a[3]), "r"(b[0]), "r"(b[1]));
}
__device__ __forceinline__ void ldm4(unsigned* r, unsigned addr) {
    asm volatile("ldmatrix.sync.aligned.m8n8.x4.shared.b16 {%0,%1,%2,%3}, [%4];"
        : "=r"(r[0]), "=r"(r[1]), "=r"(r[2]), "=r"(r[3]) : "r"(addr));
}

__global__ void k_zero() {
    if (threadIdx.x == 0 && blockIdx.x == 0) g_bar = 0u;
}

// ---- prep kernels ----
__global__ void k_prep2(const float* __restrict__ W_ih) {   // W_ih -> [v][4H]
    int idx = blockIdx.x * 256 + threadIdx.x;
    if (idx < VV * 4 * HH) {
        int v = idx >> 12, row = idx & 4095;
        g_wih_t[v * 4096 + row] = W_ih[(size_t)row * VV + v];
    }
}
__global__ void k_prepw(const float* __restrict__ Wnl) {    // Wnl -> bf16
    int i = blockIdx.x * 256 + threadIdx.x;
    if (i < HH * (HH + LL) / 2) {
        float2 v = ((const float2*)Wnl)[i];
        ((__nv_bfloat162*)g_wnlb)[i] = __floats2bfloat162_rn(v.x, v.y);
    }
}
__global__ void k_latb(const float* __restrict__ latent) {  // latent -> bf16
    int i = blockIdx.x * 256 + threadIdx.x;
    if (i < BB * LL / 2) {
        float2 v = ((const float2*)latent)[i];
        ((__nv_bfloat162*)g_latb)[i] = __floats2bfloat162_rn(v.x, v.y);
    }
}

// ------------------------------------------------------------------
// h0 = relu(latent @ Wz^T + bz) -> bf16 image [b][h]
// ------------------------------------------------------------------
__global__ void k_h0(const float* __restrict__ latent,
                     const float* __restrict__ Wz,
                     const float* __restrict__ bz) {
    __shared__ float lat[LL];
    int b = blockIdx.x;
    for (int k = threadIdx.x; k < LL; k += blockDim.x) lat[k] = latent[b * LL + k];
    __syncthreads();
    for (int j = threadIdx.x; j < HH; j += blockDim.x) {
        const float4* w = (const float4*)(Wz + (size_t)j * LL);
        float s = bz[j];
#pragma unroll 8
        for (int k4 = 0; k4 < LL / 4; ++k4) {
            float4 wv = w[k4];
            s += wv.x * lat[k4 * 4 + 0] + wv.y * lat[k4 * 4 + 1]
               + wv.z * lat[k4 * 4 + 2] + wv.w * lat[k4 * 4 + 3];
        }
        g_h0b[b * HH + j] = __float2bfloat16(fmaxf(s, 0.f));
    }
}

// ------------------------------------------------------------------
// Persistent HMMA LSTM (R11 core, B staged from bf16 hs; P separate).
// 128 CTAs, 256 threads (8 warps). CTA m: units [8m,8m+8) = 32 rows.
// ------------------------------------------------------------------
#define BUF_W  8704                 // 32 n-rows x 272B
#define LSM_P  69632                // P: 64 rows x 132 floats = 33792
#define LSM_CB 103424               // cbias 32 floats
#define LSM_SZ 103936

__global__ void __launch_bounds__(256, 1) k_lstm_mma(
    const float* __restrict__ W_hh,
    const float* __restrict__ b_ih,
    const float* __restrict__ b_hh,
    const int*   __restrict__ labels)
{
    extern __shared__ char sm[];
    float* cbias = (float*)(sm + LSM_CB);

    const int tid = threadIdx.x;
    const int w   = tid >> 5;
    const int l   = tid & 31;
    const int qr  = l >> 2;
    const int qc  = l & 3;
    const int m   = blockIdx.x;
    const int k0  = w * 128;

    if (tid < 32) {
        int u = tid >> 2, g = tid & 3;
        cbias[tid] = b_ih[g * HH + m * 8 + u] + b_hh[g * HH + m * 8 + u];
    }

    // one-time: A fragments (W_hh bf16) into registers (layout proven R11)
    unsigned af[2][8][4];
#pragma unroll
    for (int mt = 0; mt < 2; ++mt) {
        const float* wlo = W_hh + (size_t)((mt * 2 + 0) * HH + m * 8 + qr) * HH;
        const float* whi = W_hh + (size_t)((mt * 2 + 1) * HH + m * 8 + qr) * HH;
#pragma unroll
        for (int ks = 0; ks < 8; ++ks) {
            int k = k0 + ks * 16 + qc * 2;
            af[mt][ks][0] = pack_bf2(wlo[k],     wlo[k + 1]);
            af[mt][ks][1] = pack_bf2(whi[k],     whi[k + 1]);
            af[mt][ks][2] = pack_bf2(wlo[k + 8], wlo[k + 9]);
            af[mt][ks][3] = pack_bf2(whi[k + 8], whi[k + 9]);
        }
    }

    const int pu = tid & 7;
    const int pb = tid >> 3;
    float c_loc = 0.f;
    char* bufw = sm + w * BUF_W;
    __syncthreads();

    for (int t = 0; t < TT; ++t) {
        if (t > 0) {
            if (tid == 0) {
                unsigned tgt = 128u * (unsigned)t;
                while (ld_acq(&g_bar) < tgt) {}
            }
            __syncthreads();
        }

        // stage B slice: 32 batches x 256B (bf16 k-slice), coalesced
        {
            int nn = l >> 4, c = l & 15;
#pragma unroll
            for (int p = 0; p < 16; ++p) {
                int n = p * 2 + nn;
                const char* src = (t == 0)
                    ? ((const char*)g_h0b + (size_t)n * (HH * 2) + k0 * 2 + c * 16)
                    : ((const char*)g_hsb + ((size_t)n * TT + (t - 1)) * (HH * 2) + k0 * 2 + c * 16);
                *(float4*)(bufw + n * 272 + c * 16) = *(const float4*)src;
            }
        }
        __syncthreads();

        // MMA: 8 ksteps x (2 mt x 4 nt)
        float acc[2][4][4] = {};
#pragma unroll
        for (int ks = 0; ks < 8; ++ks) {
            unsigned bf[4][2];
#pragma unroll
            for (int nt = 0; nt < 4; ++nt) {
                const char* bp = bufw + (nt * 8 + qr) * 272 + (ks * 16 + qc * 2) * 2;
                bf[nt][0] = *(const unsigned*)bp;
                bf[nt][1] = *(const unsigned*)(bp + 16);
            }
#pragma unroll
            for (int mt = 0; mt < 2; ++mt)
#pragma unroll
                for (int nt = 0; nt < 4; ++nt)
                    mma16816(acc[mt][nt], af[mt][ks], bf[nt]);
        }

        // split-K partials into P (separate region — no pre-sync needed)
        float* P = (float*)(sm + LSM_P);
#pragma unroll
        for (int mt = 0; mt < 2; ++mt) {
            float* base = P + (w * 8 + qr) * 132;
            int g_lo = mt * 2, g_hi = mt * 2 + 1;
#pragma unroll
            for (int nt = 0; nt < 4; ++nt) {
                int n0 = nt * 8 + qc * 2;
                base[(n0    ) * 4 + g_lo] = acc[mt][nt][0];
                base[(n0 + 1) * 4 + g_lo] = acc[mt][nt][1];
                base[(n0    ) * 4 + g_hi] = acc[mt][nt][2];
                base[(n0 + 1) * 4 + g_hi] = acc[mt][nt][3];
            }
        }
        __syncthreads();

        // reduce 8 warps + pointwise cell (i,f,g,o)
        {
            float4 s = make_float4(0.f, 0.f, 0.f, 0.f);
#pragma unroll
            for (int ww = 0; ww < 8; ++ww) {
                float4 v = *(const float4*)(P + (ww * 8 + pu) * 132 + pb * 4);
                s.x += v.x; s.y += v.y; s.z += v.z; s.w += v.w;
            }
            float gi = s.x + cbias[pu * 4 + 0];
            float gf = s.y + cbias[pu * 4 + 1];
            float gg = s.z + cbias[pu * 4 + 2];
            float go = s.w + cbias[pu * 4 + 3];
            const int ug = m * 8 + pu;
            if (t > 0) {
                int lbl = labels[pb * TT + t - 1];
                const float* wr = g_wih_t + (size_t)lbl * 4096;
                gi += wr[0 * HH + ug];
                gf += wr[1 * HH + ug];
                gg += wr[2 * HH + ug];
                go += wr[3 * HH + ug];
            }
            float is = 1.f / (1.f + expf(-gi));
            float fs = 1.f / (1.f + expf(-gf));
            float gt = tanhf(gg);
            float os = 1.f / (1.f + expf(-go));
            c_loc = fs * c_loc + is * gt;
            g_hsb[((size_t)pb * TT + t) * HH + ug] = __float2bfloat16(os * tanhf(c_loc));
        }
        __syncthreads();
        if (tid == 0) red_rel(&g_bar, 1u);
    }
}

// ------------------------------------------------------------------
// Output head v3 (HMMA): 128 CTAs x 256 thr. CTA = 128 rows; 8 passes
// of N=128 j; K chunks of 128 staged in SMEM; warps = 4 mG x 2 nh,
// warp tile m32 x n64 via ldmatrix.x4 fragments. Epilogue: relu+bias
// -> fp32 aS, scalar V=13 logits (warp-uniform Wos reads), nll tail.
// ------------------------------------------------------------------
#define OSM_A   0           // 128 x 272 = 34816
#define OSM_B   34816       // 34816
#define OSM_AS  69632       // 128 x 133 x 4 = 68096
#define OSM_LS  137728      // 2 x 128 x 16 x 4 = 16384
#define OSM_WOS 154112      // 13 x 132 x 4 = 6864
#define OSM_BNL 160976      // 512
#define OSM_RED 161488      // 16
#define OSM_SZ  161536

__global__ void __launch_bounds__(256) k_out_mma(
    const int*   __restrict__ labels,
    const int*   __restrict__ lengths,
    const float* __restrict__ bnl,
    const float* __restrict__ Wout,
    const float* __restrict__ bout)
{
    extern __shared__ char sm[];
    const int tid = threadIdx.x, wid = tid >> 5, l = tid & 31;
    const int qr = l >> 2, qc = l & 3;
    const int mG = wid >> 1, nh = wid & 1;
    const int r0 = blockIdx.x * 128;
    const int b  = blockIdx.x >> 2;
    const unsigned smb = smem_u32(sm);

    float* LsP  = (float*)(sm + OSM_LS);
    float* aS   = (float*)(sm + OSM_AS);
    float* Wos  = (float*)(sm + OSM_WOS);
    float* bnls = (float*)(sm + OSM_BNL);
    float* red  = (float*)(sm + OSM_RED);

    for (int i = tid; i < 2 * 128 * 16; i += 256) LsP[i] = 0.f;

    // ldmatrix lane-address components (bytes added to tile base)
    const int a_row = (l & 15), a_kb = ((l >> 4) * 8) * 2;
    const int b_row = (l & 7) + ((l >> 4) << 3), b_kb = (((l >> 3) & 1) * 8) * 2;

    for (int jc = 0; jc < 8; ++jc) {
        float acc[2][8][4];
#pragma unroll
        for (int mt = 0; mt < 2; ++mt)
#pragma unroll
            for (int nt = 0; nt < 8; ++nt)
#pragma unroll
                for (int c = 0; c < 4; ++c) acc[mt][nt][c] = 0.f;

        for (int kc = 0; kc < 10; ++kc) {
            __syncthreads();   // prior compute / logits done
            // stage A chunk [128 rows][128 k] bf16 (k>=1024 -> latent)
#pragma unroll
            for (int q = 0; q < 8; ++q) {
                int idx = q * 256 + tid;
                int r = idx >> 4, seg = idx & 15;
                const char* src = (kc < 8)
                    ? ((const char*)g_hsb + (size_t)(r0 + r) * (HH * 2) + kc * 256 + seg * 16)
                    : ((const char*)g_latb + b * (LL * 2) + (kc - 8) * 256 + seg * 16);
                *(float4*)(sm + OSM_A + r * 272 + seg * 16) = *(const float4*)src;
            }
            // stage B chunk [128 j][128 k] bf16 from Wnl-bf16
#pragma unroll
            for (int q = 0; q < 8; ++q) {
                int idx = q * 256 + tid;
                int r = idx >> 4, seg = idx & 15;
                *(float4*)(sm + OSM_B + r * 272 + seg * 16) =
                    *(const float4*)((const char*)g_wnlb
                        + (size_t)(jc * 128 + r) * ((HH + LL) * 2) + kc * 256 + seg * 16);
            }
            if (kc == 0) {   // per-jc constants
                for (int i = tid; i < 128; i += 256) bnls[i] = bnl[jc * 128 + i];
                for (int i = tid; i < VV * 128; i += 256) {
                    int v = i >> 7, jl = i & 127;
                    Wos[v * 132 + jl] = Wout[(size_t)v * HH + jc * 128 + jl];
                }
            }
            __syncthreads();

            const unsigned Abase = smb + OSM_A + (unsigned)((mG * 32 + a_row) * 272) + a_kb;
            const unsigned Bbase = smb + OSM_B + (unsigned)((nh * 64 + b_row) * 272) + b_kb;
#pragma unroll
            for (int ks = 0; ks < 8; ++ks) {
                unsigned afr[2][4];
                ldm4(afr[0], Abase + ks * 32);
                ldm4(afr[1], Abase + 16 * 272 + ks * 32);
#pragma unroll
                for (int q = 0; q < 4; ++q) {
                    unsigned bfr[4];
                    ldm4(bfr, Bbase + q * 16 * 272 + ks * 32);
                    mma16816(acc[0][2 * q],     afr[0], bfr);
                    mma16816(acc[0][2 * q + 1], afr[0], bfr + 2);
                    mma16816(acc[1][2 * q],     afr[1], bfr);
                    mma16816(acc[1][2 * q + 1], afr[1], bfr + 2);
                }
            }
        }

        // relu + bias -> aS (fragment positions validated R11: c0=(qr,2qc))
#pragma unroll
        for (int mt = 0; mt < 2; ++mt)
#pragma unroll
            for (int nt = 0; nt < 8; ++nt) {
                int rowa = mG * 32 + mt * 16 + qr;
                int col = nh * 64 + nt * 8 + qc * 2;
                float b0v = bnls[col], b1v = bnls[col + 1];
                aS[rowa * 133 + col]           = fmaxf(acc[mt][nt][0] + b0v, 0.f);
                aS[rowa * 133 + col + 1]       = fmaxf(acc[mt][nt][1] + b1v, 0.f);
                aS[(rowa + 8) * 133 + col]     = fmaxf(acc[mt][nt][2] + b0v, 0.f);
                aS[(rowa + 8) * 133 + col + 1] = fmaxf(acc[mt][nt][3] + b1v, 0.f);
            }
        __syncthreads();

        // logits: thread = (row, j-half); Wos reads warp-uniform (broadcast)
        {
            int row = tid & 127, hf = tid >> 7;
            float lv[VV];
#pragma unroll
            for (int v = 0; v < VV; ++v) lv[v] = 0.f;
            for (int jl = hf * 64; jl < hf * 64 + 64; ++jl) {
                float a = aS[row * 133 + jl];
#pragma unroll
                for (int v = 0; v < VV; ++v)
                    lv[v] += a * Wos[v * 132 + jl];
            }
            float* Lp = LsP + (hf * 128 + row) * 16;
#pragma unroll
            for (int v = 0; v < VV; ++v) Lp[v] += lv[v];
        }
    }
    __syncthreads();

    // log-softmax + masked NLL
    float val = 0.f;
    if (tid < 128) {
        int row = tid;
        int grow = r0 + row;
        int t = grow & (TT - 1);
        float lg[VV];
#pragma unroll
        for (int v = 0; v < VV; ++v)
            lg[v] = LsP[row * 16 + v] + LsP[(128 + row) * 16 + v] + bout[v];
        float mx = -1e30f;
#pragma unroll
        for (int v = 0; v < VV; ++v) mx = fmaxf(mx, lg[v]);
        float s = 0.f;
#pragma unroll
        for (int v = 0; v < VV; ++v) s += expf(lg[v] - mx);
        float lse = mx + logf(s);
        int lbl = labels[b * TT + t];
        float nll = lse - lg[lbl];
        if (t < lengths[b]) val = nll;
#pragma unroll
        for (int o = 16; o > 0; o >>= 1) val += __shfl_down_sync(0xffffffffu, val, o);
        if ((tid & 31) == 0) red[tid >> 5] = val;
    }
    __syncthreads();
    if (tid == 0) g_part[blockIdx.x] = red[0] + red[1] + red[2] + red[3];
}

// ------------------------------------------------------------------
__global__ void k_final(float* __restrict__ out, int out_size) {
    int b = threadIdx.x;   // 0..31
    float s = 0.f;
#pragma unroll
    for (int i = 0; i < 4; ++i) s += g_part[b * 4 + i];
    if (1 + b < out_size) out[1 + b] = s;
    float tot = s;
#pragma unroll
    for (int o = 16; o > 0; o >>= 1) tot += __shfl_down_sync(0xffffffffu, tot, o);
    if (b == 0) out[0] = tot;
}

// ------------------------------------------------------------------
extern "C" void kernel_launch(void* const* d_in, const int* in_sizes, int n_in,
                              void* d_out, int out_size) {
    const float* latent  = (const float*)d_in[1];
    const int*   labels  = (const int*)d_in[2];
    const int*   lengths = (const int*)d_in[3];
    const float* W_ih    = (const float*)d_in[4];
    const float* W_hh    = (const float*)d_in[5];
    const float* b_ih    = (const float*)d_in[6];
    const float* b_hh    = (const float*)d_in[7];
    const float* Wz      = (const float*)d_in[8];
    const float* bz      = (const float*)d_in[9];
    const float* Wnl     = (const float*)d_in[10];
    const float* bnl     = (const float*)d_in[11];
    const float* Wout    = (const float*)d_in[12];
    const float* bout    = (const float*)d_in[13];
    float* out = (float*)d_out;

    cudaFuncSetAttribute(k_lstm_mma, cudaFuncAttributeMaxDynamicSharedMemorySize, LSM_SZ);
    cudaFuncSetAttribute(k_out_mma, cudaFuncAttributeMaxDynamicSharedMemorySize, OSM_SZ);

    k_zero<<<1, 32>>>();
    k_prep2<<<(VV * 4 * HH + 255) / 256, 256>>>(W_ih);
    k_prepw<<<(HH * (HH + LL) / 2 + 255) / 256, 256>>>(Wnl);
    k_latb<<<(BB * LL / 2 + 255) / 256, 256>>>(latent);
    k_h0<<<BB, 256>>>(latent, Wz, bz);
    k_lstm_mma<<<128, 256, LSM_SZ>>>(W_hh, b_ih, b_hh, labels);
    k_out_mma<<<128, 256, OSM_SZ>>>(labels, lengths, bnl, Wout, bout);
    k_final<<<1, 32>>>(out, out_size);
}